// round 6
// baseline (speedup 1.0000x reference)
#include <cuda_runtime.h>
#include <math.h>

#define B   4096
#define L   200
#define LF  100
#define E   64
#define P   32
#define H   32
#define IFD 128
#define TPD 3168   /* P + PNET = 32 + 3136 */

typedef unsigned long long ull;

// packed f32x2 helpers (bit-identical IEEE fp32 math, 2x fma-pipe throughput)
__device__ __forceinline__ ull pk2(float x, float y) {
    ull r; asm("mov.b64 %0, {%1,%2};" : "=l"(r) : "f"(x), "f"(y)); return r;
}
__device__ __forceinline__ void upk2(ull v, float& x, float& y) {
    asm("mov.b64 {%0,%1}, %2;" : "=f"(x), "=f"(y) : "l"(v));
}
__device__ __forceinline__ void ffma2(ull& d, ull a, ull b) {
    asm("fma.rn.f32x2 %0, %1, %2, %0;" : "+l"(d) : "l"(a), "l"(b));
}

// ---------------- scratch (device globals) ----------------
__device__ float g_prompt_input[B * E];
__device__ float g_total_prompt[(size_t)B * TPD];        // ~52 MB
__device__ float g_final_user[B * E];
__device__ float g_final_item[B * E];
__device__ float g_pos_pe[B * P];
__device__ float g_ife[B * E];
__device__ float g_ufe[B * E];

// ======================================================================
// K0: batched feature MLPs: sigmoid(features @ W + b) for item & user.
// 128 blocks x 32 rows. Weights cached in smem once per block.
// ======================================================================
__global__ __launch_bounds__(256) void k0_kernel(
    const float* __restrict__ item_features, const float* __restrict__ user_features,
    const float* __restrict__ W_if, const float* __restrict__ b_if,
    const float* __restrict__ W_uf, const float* __restrict__ b_uf)
{
    int b0 = blockIdx.x * 32;
    int tid = threadIdx.x;
    __shared__ float sW[IFD * E];    // 32 KB
    __shared__ float sF[4 * IFD];    // 2 KB
    int rr = tid >> 6, out = tid & 63;

    #pragma unroll
    for (int ph = 0; ph < 2; ph++) {
        const float* W    = ph ? W_uf : W_if;
        const float* bias = ph ? b_uf : b_if;
        const float* F    = ph ? user_features : item_features;
        float* dst        = ph ? g_ufe : g_ife;

        __syncthreads();   // protect sW overwrite vs previous phase readers
        for (int t = tid; t < IFD * E; t += 256) sW[t] = W[t];

        for (int rg = 0; rg < 8; rg++) {
            __syncthreads();
            for (int t = tid; t < 4 * IFD; t += 256)
                sF[t] = F[(size_t)(b0 + rg * 4 + (t >> 7)) * IFD + (t & 127)];
            __syncthreads();
            float acc = bias[out];
            #pragma unroll
            for (int c = 0; c < 32; c++) {
                float4 f = *(const float4*)&sF[rr * IFD + c * 4];
                acc += f.x * sW[(c*4+0) * E + out] + f.y * sW[(c*4+1) * E + out]
                     + f.z * sW[(c*4+2) * E + out] + f.w * sW[(c*4+3) * E + out];
            }
            dst[(size_t)(b0 + rg * 4 + rr) * E + out] = 1.0f / (1.0f + expf(-acc));
        }
    }
}

// ======================================================================
// K1: attention + pooling + prompt_input. History rows cached ONCE in
// dynamic smem, transposed with stride 201 (conflict-free).
// ======================================================================
#define SHS 201
__global__ __launch_bounds__(256) void k1_kernel(
    const float* __restrict__ item_emb, const float* __restrict__ user_emb,
    const int* __restrict__ user_id, const int* __restrict__ target_item_id,
    const int* __restrict__ history_item_id, const int* __restrict__ history_len,
    const int* __restrict__ item_pos_feedback, const int* __restrict__ pos_mask)
{
    extern __shared__ float SHT[];   // [64][201] = 51456 B
    int b = blockIdx.x;
    int tid = threadIdx.x;

    __shared__ float s_tgt[E];
    __shared__ float s_attn[L];
    __shared__ int   s_hidx[L];
    __shared__ int   s_pidx[LF];
    __shared__ float s_pm[LF];
    __shared__ float red[256];

    int tgt_id = target_item_id[b];
    if (tid < E) s_tgt[tid] = item_emb[(size_t)tgt_id * E + tid];
    for (int l = tid; l < L; l += 256)  s_hidx[l] = history_item_id[(size_t)b * L + l];
    for (int l = tid; l < LF; l += 256) {
        s_pidx[l] = item_pos_feedback[(size_t)b * LF + l];
        s_pm[l]   = pos_mask[(size_t)b * LF + l] ? 1.0f : 0.0f;
    }
    __syncthreads();

    // score phase: load row once, dot with tgt, scatter transposed to SHT
    int hlen = history_len[b];
    float sc = -1e30f;
    if (tid < L) {
        const float4* row = (const float4*)(item_emb + (size_t)s_hidx[tid] * E);
        float d = 0.0f;
        #pragma unroll
        for (int q = 0; q < 16; q++) {
            float4 v = row[q];
            d += v.x * s_tgt[4*q] + v.y * s_tgt[4*q+1] + v.z * s_tgt[4*q+2] + v.w * s_tgt[4*q+3];
            SHT[(4*q+0) * SHS + tid] = v.x;
            SHT[(4*q+1) * SHS + tid] = v.y;
            SHT[(4*q+2) * SHS + tid] = v.z;
            SHT[(4*q+3) * SHS + tid] = v.w;
        }
        sc = (tid < hlen) ? d * 0.125f : -1e9f;
    }
    // softmax
    red[tid] = sc; __syncthreads();
    for (int s = 128; s > 0; s >>= 1) { if (tid < s) red[tid] = fmaxf(red[tid], red[tid+s]); __syncthreads(); }
    float mx = red[0]; __syncthreads();
    float ex = (tid < L) ? expf(sc - mx) : 0.0f;
    red[tid] = ex; __syncthreads();
    for (int s = 128; s > 0; s >>= 1) { if (tid < s) red[tid] += red[tid+s]; __syncthreads(); }
    float inv = 1.0f / red[0];
    __syncthreads();
    if (tid < L) s_attn[tid] = ex * inv;
    __syncthreads();

    // history pooling from smem cache: 4 groups x 64 lanes
    int g = tid >> 6, e = tid & 63;
    {
        float acc = 0.0f;
        int base = g * 50;
        #pragma unroll 5
        for (int l = base; l < base + 50; l++)
            acc += s_attn[l] * SHT[e * SHS + l];
        red[tid] = acc;
    }
    __syncthreads();
    if (tid < 64) {
        float hp = red[tid] + red[64 + tid] + red[128 + tid] + red[192 + tid];
        int uid = user_id[b];
        g_final_user[b * E + tid] = user_emb[(size_t)uid * E + tid] + g_ufe[b * E + tid] + hp;
        g_final_item[b * E + tid] = s_tgt[tid] + g_ife[b * E + tid];
    }
    __syncthreads();

    // prompt pooling (single gmem pass)
    {
        float pacc = 0.0f;
        int base = g * 25;
        #pragma unroll 5
        for (int l = base; l < base + 25; l++)
            pacc += s_pm[l] * item_emb[(size_t)s_pidx[l] * E + e];
        red[tid] = pacc;
    }
    __syncthreads();
    if (tid < 64) {
        float s = red[tid] + red[64 + tid] + red[128 + tid] + red[192 + tid];
        float cnt = 0.0f;
        #pragma unroll 10
        for (int l = 0; l < LF; l++) cnt += s_pm[l];
        g_prompt_input[b * E + tid] = s / cnt;
    }
}

// ======================================================================
// K2 v3: Wp GEMM with f32x2. Thread tile = 16 rows x 4 cols.
// sAD holds A duplicated: (a,a) pairs for direct LDS.64 broadcast.
// grid (64, 13), block 256 = 4 row-groups x 64 col-quads.
// ======================================================================
#define JBLK 256
__global__ __launch_bounds__(256) void k2_kernel(
    const float* __restrict__ Wp, const float* __restrict__ bp)
{
    int b0 = blockIdx.x * 64;
    int jb = blockIdx.y * JBLK;
    int tid = threadIdx.x;
    __shared__ __align__(16) float sAD[64 * 128];   // 32 KB, value-duplicated

    for (int idx = tid; idx < 1024; idx += 256) {
        int r = idx >> 4, c = idx & 15;
        float4 v = *(const float4*)&g_prompt_input[(b0 + r) * E + c * 4];
        int base = (r * 64 + c * 4) * 2;
        sAD[base+0] = v.x; sAD[base+1] = v.x;
        sAD[base+2] = v.y; sAD[base+3] = v.y;
        sAD[base+4] = v.z; sAD[base+5] = v.z;
        sAD[base+6] = v.w; sAD[base+7] = v.w;
    }
    __syncthreads();

    int rg = tid >> 6;
    int jj = tid & 63;
    int j0 = jb + jj * 4;
    if (j0 >= TPD) return;
    int r0 = rg * 16;

    float4 bb = *(const float4*)&bp[j0];
    ull b01 = pk2(bb.x, bb.y), b23 = pk2(bb.z, bb.w);
    ull acc[16][2];
    #pragma unroll
    for (int i = 0; i < 16; i++) { acc[i][0] = b01; acc[i][1] = b23; }

    #pragma unroll 4
    for (int k = 0; k < 64; k++) {
        float4 w4 = *(const float4*)&Wp[(size_t)k * TPD + j0];
        ull w01 = pk2(w4.x, w4.y), w23 = pk2(w4.z, w4.w);
        #pragma unroll
        for (int i = 0; i < 16; i++) {
            ull a = *(const ull*)&sAD[((r0 + i) * 64 + k) * 2];
            ffma2(acc[i][0], a, w01);
            ffma2(acc[i][1], a, w23);
        }
    }
    #pragma unroll
    for (int i = 0; i < 16; i++) {
        float4 o;
        upk2(acc[i][0], o.x, o.y);
        upk2(acc[i][1], o.z, o.w);
        o.x = fmaxf(o.x, 0.0f); o.y = fmaxf(o.y, 0.0f);
        o.z = fmaxf(o.z, 0.0f); o.w = fmaxf(o.w, 0.0f);
        *(float4*)&g_total_prompt[(size_t)(b0 + r0 + i) * TPD + j0] = o;
    }
}

// ======================================================================
// K3 v4: register-tiled prompt MLP with f32x2 packed math.
// thread (ig<26, pg<8): 4 items x 4 units. UTD/HTD value-duplicated,
// sharing one smem buffer (sequential lifetimes).
// ======================================================================
#define NI    104
#define UTS2  208   /* duplicated u row stride */
#define HTS2  212   /* duplicated hidden row stride */

__global__ __launch_bounds__(256) void k3_kernel(
    const float* __restrict__ item_emb,
    const int* __restrict__ pos_fb, const int* __restrict__ pos_mask,
    const int* __restrict__ neg_fb, const int* __restrict__ neg_mask,
    float* __restrict__ out)
{
    int b = blockIdx.x;
    int tid = threadIdx.x;
    const float* tp = g_total_prompt + (size_t)b * TPD;

    __shared__ __align__(16) float W1[E * H];     // w1[e][h]
    __shared__ __align__(16) float W2[H * P];     // w2[h][p]
    __shared__ __align__(16) float UD[32 * HTS2]; // aliased UTD(208)/HTD(212)
    __shared__ float B1[H];
    __shared__ float B2[P];
    __shared__ int   s_fi[NI];
    __shared__ float s_fm[NI];
    __shared__ float RED[26 * 32];
    __shared__ float PE[64];

    for (int t = tid; t < 2048; t += 256) W1[t] = tp[32 + t];
    for (int t = tid; t < 1024; t += 256) W2[t] = tp[2112 + t];
    if (tid < 32) { B1[tid] = tp[2080 + tid]; B2[tid] = tp[3136 + tid]; }

    int pg = tid & 7;
    int ig = tid >> 3;
    bool act = (ig < 26);
    int p0 = pg * 4;
    int i0 = ig * 4;

    for (int br = 0; br < 2; br++) {
        const int* fb = br ? neg_fb : pos_fb;
        const int* mk = br ? neg_mask : pos_mask;
        __syncthreads();
        if (tid < NI) {
            int v = 0; float m = 0.0f;
            if (tid < LF) { v = fb[(size_t)b * LF + tid]; m = mk[(size_t)b * LF + tid] ? 1.0f : 0.0f; }
            s_fi[tid] = v; s_fm[tid] = m;
        }
        __syncthreads();

        // layer 1: acc packed along units (pp pairs), u broadcast-duplicated
        ull bb01 = pk2(B1[p0], B1[p0+1]), bb23 = pk2(B1[p0+2], B1[p0+3]);
        ull a1[4][2];
        #pragma unroll
        for (int ii = 0; ii < 4; ii++) { a1[ii][0] = bb01; a1[ii][1] = bb23; }

        #pragma unroll
        for (int ch = 0; ch < 2; ch++) {
            for (int idx = tid; idx < NI * 8; idx += 256) {
                int c4 = idx / NI;
                int i  = idx - c4 * NI;
                float4 v = *(const float4*)(item_emb + (size_t)s_fi[i] * E + ch * 32 + c4 * 4);
                UD[(c4*4+0) * UTS2 + 2*i] = v.x; UD[(c4*4+0) * UTS2 + 2*i + 1] = v.x;
                UD[(c4*4+1) * UTS2 + 2*i] = v.y; UD[(c4*4+1) * UTS2 + 2*i + 1] = v.y;
                UD[(c4*4+2) * UTS2 + 2*i] = v.z; UD[(c4*4+2) * UTS2 + 2*i + 1] = v.z;
                UD[(c4*4+3) * UTS2 + 2*i] = v.w; UD[(c4*4+3) * UTS2 + 2*i + 1] = v.w;
            }
            __syncthreads();
            if (act) {
                #pragma unroll 8
                for (int le = 0; le < 32; le++) {
                    int e = ch * 32 + le;
                    ull w01 = *(const ull*)&W1[e * H + p0];
                    ull w23 = *(const ull*)&W1[e * H + p0 + 2];
                    #pragma unroll
                    for (int ii = 0; ii < 4; ii++) {
                        ull u = *(const ull*)&UD[le * UTS2 + 2 * (i0 + ii)];
                        ffma2(a1[ii][0], u, w01);
                        ffma2(a1[ii][1], u, w23);
                    }
                }
            }
            __syncthreads();   // UTD reads done before refill / HTD overwrite
        }

        // relu + write duplicated hidden into the same buffer (stride 212)
        if (act) {
            #pragma unroll
            for (int ii = 0; ii < 4; ii++) {
                float h0, h1v, h2v, h3;
                upk2(a1[ii][0], h0, h1v);
                upk2(a1[ii][1], h2v, h3);
                h0 = fmaxf(h0, 0.0f); h1v = fmaxf(h1v, 0.0f);
                h2v = fmaxf(h2v, 0.0f); h3 = fmaxf(h3, 0.0f);
                int col = 2 * (i0 + ii);
                UD[(p0+0) * HTS2 + col] = h0;  UD[(p0+0) * HTS2 + col + 1] = h0;
                UD[(p0+1) * HTS2 + col] = h1v; UD[(p0+1) * HTS2 + col + 1] = h1v;
                UD[(p0+2) * HTS2 + col] = h2v; UD[(p0+2) * HTS2 + col + 1] = h2v;
                UD[(p0+3) * HTS2 + col] = h3;  UD[(p0+3) * HTS2 + col + 1] = h3;
            }
        }
        __syncthreads();

        // layer 2 + masked sum
        ull cb01 = pk2(B2[p0], B2[p0+1]), cb23 = pk2(B2[p0+2], B2[p0+3]);
        ull a2[4][2];
        #pragma unroll
        for (int ii = 0; ii < 4; ii++) { a2[ii][0] = cb01; a2[ii][1] = cb23; }
        if (act) {
            #pragma unroll 8
            for (int h = 0; h < 32; h++) {
                ull w01 = *(const ull*)&W2[h * P + p0];
                ull w23 = *(const ull*)&W2[h * P + p0 + 2];
                #pragma unroll
                for (int ii = 0; ii < 4; ii++) {
                    ull u = *(const ull*)&UD[h * HTS2 + 2 * (i0 + ii)];
                    ffma2(a2[ii][0], u, w01);
                    ffma2(a2[ii][1], u, w23);
                }
            }
            float part[4] = {0.0f, 0.0f, 0.0f, 0.0f};
            #pragma unroll
            for (int ii = 0; ii < 4; ii++) {
                float m = s_fm[i0 + ii];
                float v0, v1, v2, v3;
                upk2(a2[ii][0], v0, v1);
                upk2(a2[ii][1], v2, v3);
                part[0] += m * v0; part[1] += m * v1;
                part[2] += m * v2; part[3] += m * v3;
            }
            #pragma unroll
            for (int pp = 0; pp < 4; pp++) RED[ig * 32 + p0 + pp] = part[pp];
        }
        __syncthreads();

        if (tid < 32) {
            float s = 0.0f;
            #pragma unroll
            for (int q = 0; q < 26; q++) s += RED[q * 32 + tid];
            PE[br * 32 + tid] = s;
        }
    }
    __syncthreads();

    if (tid < 32) {
        float pos = PE[tid], neg = PE[32 + tid];
        g_pos_pe[b * 32 + tid] = pos;
        float x = neg - pos;  // softplus(-(pos-neg)) == softplus(neg-pos)
        out[B + b * 32 + tid] = fmaxf(x, 0.0f) + log1pf(expf(-fabsf(x)));
    }
}

// ======================================================================
// K4: fusion MLP + dot. 4 rows/block, 1024 blocks (occupancy fix).
// ======================================================================
__global__ __launch_bounds__(256) void k4_kernel(
    const float* __restrict__ Wf1, const float* __restrict__ bf1,
    const float* __restrict__ Wf2, const float* __restrict__ bf2,
    const float* __restrict__ Wf3, float* __restrict__ out)
{
    int b0 = blockIdx.x * 4;
    int tid = threadIdx.x;
    __shared__ float fin[4 * 128];
    __shared__ float h1[4 * 200];
    __shared__ float h2[4 * 80];
    __shared__ float fu[4 * 64];

    for (int t = tid; t < 4 * 128; t += 256) {
        int r = t >> 7, c = t & 127;
        int bb = b0 + r;
        float v;
        if (c < 64)      v = g_final_item[bb * 64 + c];
        else if (c < 96) v = g_pos_pe[bb * 32 + (c - 64)];
        else             v = g_total_prompt[(size_t)bb * TPD + (c - 96)];
        fin[t] = v;
    }
    __syncthreads();

    if (tid < 200) {
        float acc[4];
        #pragma unroll
        for (int r = 0; r < 4; r++) acc[r] = bf1[tid];
        #pragma unroll 4
        for (int k = 0; k < 128; k++) {
            float w = Wf1[k * 200 + tid];
            #pragma unroll
            for (int r = 0; r < 4; r++) acc[r] += fin[r * 128 + k] * w;
        }
        #pragma unroll
        for (int r = 0; r < 4; r++) h1[r * 200 + tid] = acc[r] > 0.0f ? acc[r] : 0.0f;
    }
    __syncthreads();

    if (tid < 80) {
        float acc[4];
        #pragma unroll
        for (int r = 0; r < 4; r++) acc[r] = bf2[tid];
        #pragma unroll 4
        for (int k = 0; k < 200; k++) {
            float w = Wf2[k * 80 + tid];
            #pragma unroll
            for (int r = 0; r < 4; r++) acc[r] += h1[r * 200 + k] * w;
        }
        #pragma unroll
        for (int r = 0; r < 4; r++) h2[r * 80 + tid] = acc[r] > 0.0f ? acc[r] : 0.0f;
    }
    __syncthreads();

    if (tid < 64) {
        float acc[4];
        #pragma unroll
        for (int r = 0; r < 4; r++) acc[r] = 0.0f;
        #pragma unroll 4
        for (int k = 0; k < 80; k++) {
            float w = Wf3[k * 64 + tid];
            #pragma unroll
            for (int r = 0; r < 4; r++) acc[r] += h2[r * 80 + k] * w;
        }
        #pragma unroll
        for (int r = 0; r < 4; r++) fu[r * 64 + tid] = acc[r];
    }
    __syncthreads();

    int r = tid >> 5, lane = tid & 31;
    if (r < 4) {
        int bb = b0 + r;
        float par = g_final_user[bb * 64 + lane]      * fu[r * 64 + lane]
                  + g_final_user[bb * 64 + 32 + lane] * fu[r * 64 + 32 + lane];
        #pragma unroll
        for (int s = 16; s > 0; s >>= 1) par += __shfl_xor_sync(0xffffffff, par, s);
        if (lane == 0) out[bb] = par;
    }
}

// ======================================================================
extern "C" void kernel_launch(void* const* d_in, const int* in_sizes, int n_in,
                              void* d_out, int out_size)
{
    const float* item_emb        = (const float*)d_in[0];
    const float* user_emb        = (const float*)d_in[1];
    const float* W_if            = (const float*)d_in[2];
    const float* b_if            = (const float*)d_in[3];
    const float* W_uf            = (const float*)d_in[4];
    const float* b_uf            = (const float*)d_in[5];
    const float* Wp              = (const float*)d_in[6];
    const float* bp              = (const float*)d_in[7];
    const float* Wf1             = (const float*)d_in[8];
    const float* bf1             = (const float*)d_in[9];
    const float* Wf2             = (const float*)d_in[10];
    const float* bf2             = (const float*)d_in[11];
    const float* Wf3             = (const float*)d_in[12];
    const float* item_features   = (const float*)d_in[13];
    const float* user_features   = (const float*)d_in[14];
    const int*   user_id         = (const int*)d_in[15];
    const int*   target_item_id  = (const int*)d_in[16];
    const int*   history_item_id = (const int*)d_in[17];
    const int*   history_len     = (const int*)d_in[18];
    const int*   pos_fb          = (const int*)d_in[19];
    const int*   pos_mask        = (const int*)d_in[20];
    const int*   neg_fb          = (const int*)d_in[21];
    const int*   neg_mask        = (const int*)d_in[22];
    float* out = (float*)d_out;

    const int k1_dyn = 64 * SHS * sizeof(float);   // 51456 B
    cudaFuncSetAttribute(k1_kernel, cudaFuncAttributeMaxDynamicSharedMemorySize, k1_dyn);

    k0_kernel<<<B / 32, 256>>>(item_features, user_features, W_if, b_if, W_uf, b_uf);
    k1_kernel<<<B, 256, k1_dyn>>>(item_emb, user_emb, user_id, target_item_id,
                                  history_item_id, history_len, pos_fb, pos_mask);
    k2_kernel<<<dim3(64, (TPD + JBLK - 1) / JBLK), 256>>>(Wp, bp);
    k3_kernel<<<B, 256>>>(item_emb, pos_fb, pos_mask, neg_fb, neg_mask, out);
    k4_kernel<<<B / 4, 256>>>(Wf1, bf1, Wf2, bf2, Wf3, out);
}

// round 7
// speedup vs baseline: 1.1061x; 1.1061x over previous
#include <cuda_runtime.h>
#include <math.h>

#define B   4096
#define L   200
#define LF  100
#define E   64
#define P   32
#define H   32
#define IFD 128
#define TPD 3168   /* P + PNET = 32 + 3136 */

typedef unsigned long long ull;

// packed f32x2 helpers (used by K2; bit-identical IEEE fp32 math)
__device__ __forceinline__ ull pk2(float x, float y) {
    ull r; asm("mov.b64 %0, {%1,%2};" : "=l"(r) : "f"(x), "f"(y)); return r;
}
__device__ __forceinline__ void upk2(ull v, float& x, float& y) {
    asm("mov.b64 {%0,%1}, %2;" : "=f"(x), "=f"(y) : "l"(v));
}
__device__ __forceinline__ void ffma2(ull& d, ull a, ull b) {
    asm("fma.rn.f32x2 %0, %1, %2, %0;" : "+l"(d) : "l"(a), "l"(b));
}

// ---------------- scratch (device globals) ----------------
__device__ float g_prompt_input[B * E];
__device__ float g_total_prompt[(size_t)B * TPD];        // ~52 MB
__device__ float g_final_user[B * E];
__device__ float g_final_item[B * E];
__device__ float g_pos_pe[B * P];
__device__ float g_ife[B * E];
__device__ float g_ufe[B * E];

// ======================================================================
// K0: batched feature MLPs: sigmoid(features @ W + b) for item & user.
// ======================================================================
__global__ __launch_bounds__(256) void k0_kernel(
    const float* __restrict__ item_features, const float* __restrict__ user_features,
    const float* __restrict__ W_if, const float* __restrict__ b_if,
    const float* __restrict__ W_uf, const float* __restrict__ b_uf)
{
    int b0 = blockIdx.x * 32;
    int tid = threadIdx.x;
    __shared__ float sW[IFD * E];    // 32 KB
    __shared__ float sF[4 * IFD];    // 2 KB
    int rr = tid >> 6, out = tid & 63;

    #pragma unroll
    for (int ph = 0; ph < 2; ph++) {
        const float* W    = ph ? W_uf : W_if;
        const float* bias = ph ? b_uf : b_if;
        const float* F    = ph ? user_features : item_features;
        float* dst        = ph ? g_ufe : g_ife;

        __syncthreads();
        for (int t = tid; t < IFD * E; t += 256) sW[t] = W[t];

        for (int rg = 0; rg < 8; rg++) {
            __syncthreads();
            for (int t = tid; t < 4 * IFD; t += 256)
                sF[t] = F[(size_t)(b0 + rg * 4 + (t >> 7)) * IFD + (t & 127)];
            __syncthreads();
            float acc = bias[out];
            #pragma unroll
            for (int c = 0; c < 32; c++) {
                float4 f = *(const float4*)&sF[rr * IFD + c * 4];
                acc += f.x * sW[(c*4+0) * E + out] + f.y * sW[(c*4+1) * E + out]
                     + f.z * sW[(c*4+2) * E + out] + f.w * sW[(c*4+3) * E + out];
            }
            dst[(size_t)(b0 + rg * 4 + rr) * E + out] = 1.0f / (1.0f + expf(-acc));
        }
    }
}

// ======================================================================
// K1: attention + pooling + prompt_input. History cached transposed.
// ======================================================================
#define SHS 201
__global__ __launch_bounds__(256) void k1_kernel(
    const float* __restrict__ item_emb, const float* __restrict__ user_emb,
    const int* __restrict__ user_id, const int* __restrict__ target_item_id,
    const int* __restrict__ history_item_id, const int* __restrict__ history_len,
    const int* __restrict__ item_pos_feedback, const int* __restrict__ pos_mask)
{
    extern __shared__ float SHT[];   // [64][201] = 51456 B
    int b = blockIdx.x;
    int tid = threadIdx.x;

    __shared__ float s_tgt[E];
    __shared__ float s_attn[L];
    __shared__ int   s_hidx[L];
    __shared__ int   s_pidx[LF];
    __shared__ float s_pm[LF];
    __shared__ float red[256];

    int tgt_id = target_item_id[b];
    if (tid < E) s_tgt[tid] = item_emb[(size_t)tgt_id * E + tid];
    for (int l = tid; l < L; l += 256)  s_hidx[l] = history_item_id[(size_t)b * L + l];
    for (int l = tid; l < LF; l += 256) {
        s_pidx[l] = item_pos_feedback[(size_t)b * LF + l];
        s_pm[l]   = pos_mask[(size_t)b * LF + l] ? 1.0f : 0.0f;
    }
    __syncthreads();

    int hlen = history_len[b];
    float sc = -1e30f;
    if (tid < L) {
        const float4* row = (const float4*)(item_emb + (size_t)s_hidx[tid] * E);
        float d = 0.0f;
        #pragma unroll
        for (int q = 0; q < 16; q++) {
            float4 v = row[q];
            d += v.x * s_tgt[4*q] + v.y * s_tgt[4*q+1] + v.z * s_tgt[4*q+2] + v.w * s_tgt[4*q+3];
            SHT[(4*q+0) * SHS + tid] = v.x;
            SHT[(4*q+1) * SHS + tid] = v.y;
            SHT[(4*q+2) * SHS + tid] = v.z;
            SHT[(4*q+3) * SHS + tid] = v.w;
        }
        sc = (tid < hlen) ? d * 0.125f : -1e9f;
    }
    red[tid] = sc; __syncthreads();
    for (int s = 128; s > 0; s >>= 1) { if (tid < s) red[tid] = fmaxf(red[tid], red[tid+s]); __syncthreads(); }
    float mx = red[0]; __syncthreads();
    float ex = (tid < L) ? expf(sc - mx) : 0.0f;
    red[tid] = ex; __syncthreads();
    for (int s = 128; s > 0; s >>= 1) { if (tid < s) red[tid] += red[tid+s]; __syncthreads(); }
    float inv = 1.0f / red[0];
    __syncthreads();
    if (tid < L) s_attn[tid] = ex * inv;
    __syncthreads();

    int g = tid >> 6, e = tid & 63;
    {
        float acc = 0.0f;
        int base = g * 50;
        #pragma unroll 5
        for (int l = base; l < base + 50; l++)
            acc += s_attn[l] * SHT[e * SHS + l];
        red[tid] = acc;
    }
    __syncthreads();
    if (tid < 64) {
        float hp = red[tid] + red[64 + tid] + red[128 + tid] + red[192 + tid];
        int uid = user_id[b];
        g_final_user[b * E + tid] = user_emb[(size_t)uid * E + tid] + g_ufe[b * E + tid] + hp;
        g_final_item[b * E + tid] = s_tgt[tid] + g_ife[b * E + tid];
    }
    __syncthreads();

    {
        float pacc = 0.0f;
        int base = g * 25;
        #pragma unroll 5
        for (int l = base; l < base + 25; l++)
            pacc += s_pm[l] * item_emb[(size_t)s_pidx[l] * E + e];
        red[tid] = pacc;
    }
    __syncthreads();
    if (tid < 64) {
        float s = red[tid] + red[64 + tid] + red[128 + tid] + red[192 + tid];
        float cnt = 0.0f;
        #pragma unroll 10
        for (int l = 0; l < LF; l++) cnt += s_pm[l];
        g_prompt_input[b * E + tid] = s / cnt;
    }
}

// ======================================================================
// K2: Wp GEMM with f32x2 (pack-free: A duplicated once in smem).
// ======================================================================
#define JBLK 256
__global__ __launch_bounds__(256) void k2_kernel(
    const float* __restrict__ Wp, const float* __restrict__ bp)
{
    int b0 = blockIdx.x * 64;
    int jb = blockIdx.y * JBLK;
    int tid = threadIdx.x;
    __shared__ __align__(16) float sAD[64 * 128];   // 32 KB, value-duplicated

    for (int idx = tid; idx < 1024; idx += 256) {
        int r = idx >> 4, c = idx & 15;
        float4 v = *(const float4*)&g_prompt_input[(b0 + r) * E + c * 4];
        int base = (r * 64 + c * 4) * 2;
        sAD[base+0] = v.x; sAD[base+1] = v.x;
        sAD[base+2] = v.y; sAD[base+3] = v.y;
        sAD[base+4] = v.z; sAD[base+5] = v.z;
        sAD[base+6] = v.w; sAD[base+7] = v.w;
    }
    __syncthreads();

    int rg = tid >> 6;
    int jj = tid & 63;
    int j0 = jb + jj * 4;
    if (j0 >= TPD) return;
    int r0 = rg * 16;

    float4 bb = *(const float4*)&bp[j0];
    ull b01 = pk2(bb.x, bb.y), b23 = pk2(bb.z, bb.w);
    ull acc[16][2];
    #pragma unroll
    for (int i = 0; i < 16; i++) { acc[i][0] = b01; acc[i][1] = b23; }

    #pragma unroll 4
    for (int k = 0; k < 64; k++) {
        float4 w4 = *(const float4*)&Wp[(size_t)k * TPD + j0];
        ull w01 = pk2(w4.x, w4.y), w23 = pk2(w4.z, w4.w);
        #pragma unroll
        for (int i = 0; i < 16; i++) {
            ull a = *(const ull*)&sAD[((r0 + i) * 64 + k) * 2];
            ffma2(acc[i][0], a, w01);
            ffma2(acc[i][1], a, w23);
        }
    }
    #pragma unroll
    for (int i = 0; i < 16; i++) {
        float4 o;
        upk2(acc[i][0], o.x, o.y);
        upk2(acc[i][1], o.z, o.w);
        o.x = fmaxf(o.x, 0.0f); o.y = fmaxf(o.y, 0.0f);
        o.z = fmaxf(o.z, 0.0f); o.w = fmaxf(o.w, 0.0f);
        *(float4*)&g_total_prompt[(size_t)(b0 + r0 + i) * TPD + j0] = o;
    }
}

// ======================================================================
// K3 v5: prompt MLP, pos+neg merged (208 items), 4 items x 8 units/thread.
// 52 ig x 4 pg = 208 active threads. Scalar float4: 1.5 B/FMA crossbar.
// UD buffer aliased: UT [32e][208] then HT [32h][208].
// ======================================================================
#define NT 208

__global__ __launch_bounds__(256) void k3_kernel(
    const float* __restrict__ item_emb,
    const int* __restrict__ pos_fb, const int* __restrict__ pos_mask,
    const int* __restrict__ neg_fb, const int* __restrict__ neg_mask,
    float* __restrict__ out)
{
    int b = blockIdx.x;
    int tid = threadIdx.x;
    const float* tp = g_total_prompt + (size_t)b * TPD;

    __shared__ __align__(16) float W1[E * H];     // 8 KB  w1[e][h]
    __shared__ __align__(16) float W2[H * P];     // 4 KB  w2[h][p]
    __shared__ __align__(16) float UD[32 * NT];   // 26 KB aliased UT/HT
    __shared__ float B1[H];
    __shared__ float B2[P];
    __shared__ int   s_fi[NT];
    __shared__ float s_fm[NT];
    __shared__ float RED[52 * 32];                // 6.5 KB
    __shared__ float PE[64];

    for (int t = tid; t < 2048; t += 256) W1[t] = tp[32 + t];
    for (int t = tid; t < 1024; t += 256) W2[t] = tp[2112 + t];
    if (tid < 32) { B1[tid] = tp[2080 + tid]; B2[tid] = tp[3136 + tid]; }

    // indices+masks for both branches: items [0,104) pos, [104,208) neg
    if (tid < NT) {
        int br = tid >= 104;
        int l  = tid - br * 104;
        int v = 0; float m = 0.0f;
        if (l < LF) {
            const int* fb = br ? neg_fb : pos_fb;
            const int* mk = br ? neg_mask : pos_mask;
            v = fb[(size_t)b * LF + l];
            m = mk[(size_t)b * LF + l] ? 1.0f : 0.0f;
        }
        s_fi[tid] = v; s_fm[tid] = m;
    }
    __syncthreads();

    int pg = tid & 3;
    int ig = tid >> 2;          // 0..63, active < 52
    bool act = (ig < 52);
    int p0 = pg * 8;
    int i0 = ig * 4;

    // ---------------- layer 1 ----------------
    float a1[4][8];
    #pragma unroll
    for (int ii = 0; ii < 4; ii++)
        #pragma unroll
        for (int j = 0; j < 8; j++) a1[ii][j] = B1[p0 + j];

    #pragma unroll
    for (int ch = 0; ch < 2; ch++) {
        // fill UT chunk: UD[le][i] = emb[item i][ch*32+le]
        for (int idx = tid; idx < NT * 8; idx += 256) {
            int c4 = idx / NT;
            int i  = idx - c4 * NT;
            float4 v = *(const float4*)(item_emb + (size_t)s_fi[i] * E + ch * 32 + c4 * 4);
            UD[(c4*4+0) * NT + i] = v.x;
            UD[(c4*4+1) * NT + i] = v.y;
            UD[(c4*4+2) * NT + i] = v.z;
            UD[(c4*4+3) * NT + i] = v.w;
        }
        __syncthreads();
        if (act) {
            #pragma unroll 8
            for (int le = 0; le < 32; le++) {
                int e = ch * 32 + le;
                float4 u  = *(const float4*)&UD[le * NT + i0];
                float4 wa = *(const float4*)&W1[e * H + p0];
                float4 wb = *(const float4*)&W1[e * H + p0 + 4];
                #pragma unroll
                for (int ii = 0; ii < 4; ii++) {
                    float uv = (&u.x)[ii];
                    a1[ii][0] += uv * wa.x; a1[ii][1] += uv * wa.y;
                    a1[ii][2] += uv * wa.z; a1[ii][3] += uv * wa.w;
                    a1[ii][4] += uv * wb.x; a1[ii][5] += uv * wb.y;
                    a1[ii][6] += uv * wb.z; a1[ii][7] += uv * wb.w;
                }
            }
        }
        __syncthreads();   // UT reads done before refill / HT overwrite
    }

    // relu -> HT[h][i] (reuses UD)
    if (act) {
        #pragma unroll
        for (int j = 0; j < 8; j++) {
            float4 hv;
            hv.x = fmaxf(a1[0][j], 0.0f);
            hv.y = fmaxf(a1[1][j], 0.0f);
            hv.z = fmaxf(a1[2][j], 0.0f);
            hv.w = fmaxf(a1[3][j], 0.0f);
            *(float4*)&UD[(p0 + j) * NT + i0] = hv;
        }
    }
    __syncthreads();

    // ---------------- layer 2 + masked sum ----------------
    float a2[4][8];
    #pragma unroll
    for (int ii = 0; ii < 4; ii++)
        #pragma unroll
        for (int j = 0; j < 8; j++) a2[ii][j] = B2[p0 + j];

    if (act) {
        #pragma unroll 8
        for (int h = 0; h < 32; h++) {
            float4 u  = *(const float4*)&UD[h * NT + i0];
            float4 wa = *(const float4*)&W2[h * P + p0];
            float4 wb = *(const float4*)&W2[h * P + p0 + 4];
            #pragma unroll
            for (int ii = 0; ii < 4; ii++) {
                float uv = (&u.x)[ii];
                a2[ii][0] += uv * wa.x; a2[ii][1] += uv * wa.y;
                a2[ii][2] += uv * wa.z; a2[ii][3] += uv * wa.w;
                a2[ii][4] += uv * wb.x; a2[ii][5] += uv * wb.y;
                a2[ii][6] += uv * wb.z; a2[ii][7] += uv * wb.w;
            }
        }
        float part[8] = {0,0,0,0,0,0,0,0};
        #pragma unroll
        for (int ii = 0; ii < 4; ii++) {
            float m = s_fm[i0 + ii];
            #pragma unroll
            for (int j = 0; j < 8; j++) part[j] += m * a2[ii][j];
        }
        #pragma unroll
        for (int j = 0; j < 8; j += 4)
            *(float4*)&RED[ig * 32 + p0 + j] = make_float4(part[j], part[j+1], part[j+2], part[j+3]);
    }
    __syncthreads();

    if (tid < 32) {
        float pos = 0.0f, neg = 0.0f;
        #pragma unroll
        for (int q = 0; q < 26; q++) pos += RED[q * 32 + tid];
        #pragma unroll
        for (int q = 26; q < 52; q++) neg += RED[q * 32 + tid];
        g_pos_pe[b * 32 + tid] = pos;
        float x = neg - pos;  // softplus(-(pos-neg)) == softplus(neg-pos)
        out[B + b * 32 + tid] = fmaxf(x, 0.0f) + log1pf(expf(-fabsf(x)));
    }
}

// ======================================================================
// K4: fusion MLP + dot. 4 rows/block, 1024 blocks.
// ======================================================================
__global__ __launch_bounds__(256) void k4_kernel(
    const float* __restrict__ Wf1, const float* __restrict__ bf1,
    const float* __restrict__ Wf2, const float* __restrict__ bf2,
    const float* __restrict__ Wf3, float* __restrict__ out)
{
    int b0 = blockIdx.x * 4;
    int tid = threadIdx.x;
    __shared__ float fin[4 * 128];
    __shared__ float h1[4 * 200];
    __shared__ float h2[4 * 80];
    __shared__ float fu[4 * 64];

    for (int t = tid; t < 4 * 128; t += 256) {
        int r = t >> 7, c = t & 127;
        int bb = b0 + r;
        float v;
        if (c < 64)      v = g_final_item[bb * 64 + c];
        else if (c < 96) v = g_pos_pe[bb * 32 + (c - 64)];
        else             v = g_total_prompt[(size_t)bb * TPD + (c - 96)];
        fin[t] = v;
    }
    __syncthreads();

    if (tid < 200) {
        float acc[4];
        #pragma unroll
        for (int r = 0; r < 4; r++) acc[r] = bf1[tid];
        #pragma unroll 4
        for (int k = 0; k < 128; k++) {
            float w = Wf1[k * 200 + tid];
            #pragma unroll
            for (int r = 0; r < 4; r++) acc[r] += fin[r * 128 + k] * w;
        }
        #pragma unroll
        for (int r = 0; r < 4; r++) h1[r * 200 + tid] = acc[r] > 0.0f ? acc[r] : 0.0f;
    }
    __syncthreads();

    if (tid < 80) {
        float acc[4];
        #pragma unroll
        for (int r = 0; r < 4; r++) acc[r] = bf2[tid];
        #pragma unroll 4
        for (int k = 0; k < 200; k++) {
            float w = Wf2[k * 80 + tid];
            #pragma unroll
            for (int r = 0; r < 4; r++) acc[r] += h1[r * 200 + k] * w;
        }
        #pragma unroll
        for (int r = 0; r < 4; r++) h2[r * 80 + tid] = acc[r] > 0.0f ? acc[r] : 0.0f;
    }
    __syncthreads();

    if (tid < 64) {
        float acc[4];
        #pragma unroll
        for (int r = 0; r < 4; r++) acc[r] = 0.0f;
        #pragma unroll 4
        for (int k = 0; k < 80; k++) {
            float w = Wf3[k * 64 + tid];
            #pragma unroll
            for (int r = 0; r < 4; r++) acc[r] += h2[r * 80 + k] * w;
        }
        #pragma unroll
        for (int r = 0; r < 4; r++) fu[r * 64 + tid] = acc[r];
    }
    __syncthreads();

    int r = tid >> 5, lane = tid & 31;
    if (r < 4) {
        int bb = b0 + r;
        float par = g_final_user[bb * 64 + lane]      * fu[r * 64 + lane]
                  + g_final_user[bb * 64 + 32 + lane] * fu[r * 64 + 32 + lane];
        #pragma unroll
        for (int s = 16; s > 0; s >>= 1) par += __shfl_xor_sync(0xffffffff, par, s);
        if (lane == 0) out[bb] = par;
    }
}

// ======================================================================
extern "C" void kernel_launch(void* const* d_in, const int* in_sizes, int n_in,
                              void* d_out, int out_size)
{
    const float* item_emb        = (const float*)d_in[0];
    const float* user_emb        = (const float*)d_in[1];
    const float* W_if            = (const float*)d_in[2];
    const float* b_if            = (const float*)d_in[3];
    const float* W_uf            = (const float*)d_in[4];
    const float* b_uf            = (const float*)d_in[5];
    const float* Wp              = (const float*)d_in[6];
    const float* bp              = (const float*)d_in[7];
    const float* Wf1             = (const float*)d_in[8];
    const float* bf1             = (const float*)d_in[9];
    const float* Wf2             = (const float*)d_in[10];
    const float* bf2             = (const float*)d_in[11];
    const float* Wf3             = (const float*)d_in[12];
    const float* item_features   = (const float*)d_in[13];
    const float* user_features   = (const float*)d_in[14];
    const int*   user_id         = (const int*)d_in[15];
    const int*   target_item_id  = (const int*)d_in[16];
    const int*   history_item_id = (const int*)d_in[17];
    const int*   history_len     = (const int*)d_in[18];
    const int*   pos_fb          = (const int*)d_in[19];
    const int*   pos_mask        = (const int*)d_in[20];
    const int*   neg_fb          = (const int*)d_in[21];
    const int*   neg_mask        = (const int*)d_in[22];
    float* out = (float*)d_out;

    const int k1_dyn = 64 * SHS * sizeof(float);   // 51456 B
    cudaFuncSetAttribute(k1_kernel, cudaFuncAttributeMaxDynamicSharedMemorySize, k1_dyn);

    k0_kernel<<<B / 32, 256>>>(item_features, user_features, W_if, b_if, W_uf, b_uf);
    k1_kernel<<<B, 256, k1_dyn>>>(item_emb, user_emb, user_id, target_item_id,
                                  history_item_id, history_len, pos_fb, pos_mask);
    k2_kernel<<<dim3(64, (TPD + JBLK - 1) / JBLK), 256>>>(Wp, bp);
    k3_kernel<<<B, 256>>>(item_emb, pos_fb, pos_mask, neg_fb, neg_mask, out);
    k4_kernel<<<B / 4, 256>>>(Wf1, bf1, Wf2, bf2, Wf3, out);
}